// round 17
// baseline (speedup 1.0000x reference)
#include <cuda_runtime.h>
#include <cuda_fp16.h>
#include <stdint.h>

// Problem constants
#define BB   4
#define TT   2048
#define CC   1024
#define HH   16
#define DD   64
#define BHTD (BB * HH * TT * DD)

// Scratch (device globals)
__device__ __half g_qkvh[3ull * BHTD];           // [3][B,H,T,D] fp16
__device__ __half g_atth[(size_t)BB * TT * CC];  // [B,T,C] fp16
__device__ __half g_xh[(size_t)BB * TT * CC];    // fp16(x)
__device__ __half g_wqh[3 * CC * CC];            // fp16(qkv_w)
__device__ __half g_wph[CC * CC];                // fp16(proj_w)

// ---------------------------------------------------------------------------
// helpers
// ---------------------------------------------------------------------------
__device__ __forceinline__ float ex2(float x) {
    float r;
    asm("ex2.approx.f32 %0, %1;" : "=f"(r) : "f"(x));
    return r;
}

__device__ __forceinline__ void mma16(float* c,
    uint32_t a0, uint32_t a1, uint32_t a2, uint32_t a3,
    uint32_t b0, uint32_t b1)
{
    asm volatile(
        "mma.sync.aligned.m16n8k16.row.col.f32.f16.f16.f32 "
        "{%0,%1,%2,%3},{%4,%5,%6,%7},{%8,%9},{%0,%1,%2,%3};"
        : "+f"(c[0]), "+f"(c[1]), "+f"(c[2]), "+f"(c[3])
        : "r"(a0), "r"(a1), "r"(a2), "r"(a3), "r"(b0), "r"(b1));
}

__device__ __forceinline__ void ldsm4(uint32_t& r0, uint32_t& r1,
                                      uint32_t& r2, uint32_t& r3, uint32_t addr)
{
    asm volatile("ldmatrix.sync.aligned.m8n8.x4.shared.b16 {%0,%1,%2,%3}, [%4];"
                 : "=r"(r0), "=r"(r1), "=r"(r2), "=r"(r3) : "r"(addr));
}
__device__ __forceinline__ void ldsm4t(uint32_t& r0, uint32_t& r1,
                                       uint32_t& r2, uint32_t& r3, uint32_t addr)
{
    asm volatile("ldmatrix.sync.aligned.m8n8.x4.trans.shared.b16 {%0,%1,%2,%3}, [%4];"
                 : "=r"(r0), "=r"(r1), "=r"(r2), "=r"(r3) : "r"(addr));
}

__device__ __forceinline__ void cp16(uint32_t smem, const void* gmem) {
    asm volatile("cp.async.cg.shared.global [%0], [%1], 16;\n"
                 :: "r"(smem), "l"(gmem));
}
__device__ __forceinline__ void cp16ca(uint32_t smem, const void* gmem) {
    asm volatile("cp.async.ca.shared.global [%0], [%1], 16;\n"
                 :: "r"(smem), "l"(gmem));
}
__device__ __forceinline__ void cp_commit() {
    asm volatile("cp.async.commit_group;\n" ::: "memory");
}
template <int N>
__device__ __forceinline__ void cp_wait() {
    asm volatile("cp.async.wait_group %0;\n" :: "n"(N) : "memory");
}

// ---------------------------------------------------------------------------
// Convert all fp32 operands to fp16 (one launch)
// ---------------------------------------------------------------------------
#define N4_X  (BB * TT * CC / 4)
#define N4_WQ (3 * CC * CC / 4)
#define N4_WP (CC * CC / 4)

__global__ __launch_bounds__(256) void cvt_all(
    const float4* __restrict__ x, const float4* __restrict__ wq,
    const float4* __restrict__ wp)
{
    int total = N4_X + N4_WQ + N4_WP;
    int i = blockIdx.x * blockDim.x + threadIdx.x;
    int stride = gridDim.x * blockDim.x;
    for (; i < total; i += stride) {
        const float4* in; __half* out; int j;
        if (i < N4_X)              { in = x;  out = g_xh;  j = i; }
        else if (i < N4_X + N4_WQ) { in = wq; out = g_wqh; j = i - N4_X; }
        else                       { in = wp; out = g_wph; j = i - N4_X - N4_WQ; }
        float4 v = in[j];
        __half2 h0 = __floats2half2_rn(v.x, v.y);
        __half2 h1 = __floats2half2_rn(v.z, v.w);
        *(uint2*)(out + (size_t)j * 4) =
            make_uint2(*(uint32_t*)&h0, *(uint32_t*)&h1);
    }
}

// ===========================================================================
// FP16 tensor-core GEMM v8: CTA 128x256x64, 512 threads = 16 warps,
// warp tile 64x32 (2x8 warp grid) -> 4 warps/SMSP for latency hiding.
// m16n8k16 HMMA, LDSM loads, 3-stage cp.async ring.
// ===========================================================================
#define GBM 128
#define GBN 256
#define GBK 64
#define GTPB 512
#define A_HALVES (GBM * GBK)
#define B_HALVES (GBN * GBK)
#define STAGE_BYTES ((A_HALVES + B_HALVES) * 2)
#define NSTAGE 3
#define SMEM_GEMM (NSTAGE * STAGE_BYTES)

__global__ __launch_bounds__(GTPB, 1) void gemm_h(
    const __half* __restrict__ A, const __half* __restrict__ Bt,
    const float* __restrict__ bias, float* __restrict__ Cout,
    int M, int N, int K, int mode)
{
    extern __shared__ char smc[];
    int tid = threadIdx.x, lane = tid & 31, w = tid >> 5;
    int wm0 = (w >> 3) * 64;      // 2 warps along M
    int wn0 = (w & 7) * 32;       // 8 warps along N
    int m0 = blockIdx.y * GBM, n0 = blockIdx.x * GBN;

    uint32_t smem_base = (uint32_t)__cvta_generic_to_shared(smc);

    float acc[4][4][4];
#pragma unroll
    for (int mt = 0; mt < 4; mt++)
#pragma unroll
        for (int nt = 0; nt < 4; nt++)
#pragma unroll
            for (int j = 0; j < 4; j++) acc[mt][nt][j] = 0.f;

    int keyx = lane & 7;
    uint32_t ha = lane >> 4;
    uint32_t hb = (lane >> 3) & 1;
    uint32_t aab[4], bab[2];
#pragma unroll
    for (int mt = 0; mt < 4; mt++)
        aab[mt] = (uint32_t)(wm0 + mt * 16 + (lane & 15)) * 128u;
#pragma unroll
    for (int p = 0; p < 2; p++)
        bab[p] = (uint32_t)(wn0 + p * 16 + (lane & 7) + ((lane >> 4) << 3)) * 128u;

    int nK = K / GBK;

    // staging: A 2 chunks/thread, B 4 chunks/thread (chunk = 16B)
    auto stage_tile = [&](int st, int kk) {
        uint32_t sA = smem_base + (uint32_t)st * STAGE_BYTES;
        uint32_t sB = sA + A_HALVES * 2;
#pragma unroll
        for (int i = 0; i < 2; i++) {
            int l = tid + i * GTPB;
            int row = l >> 3, q = l & 7;
            uint32_t soff = (uint32_t)row * 128u + (uint32_t)((q ^ (row & 7)) << 4);
            cp16(sA + soff, A + (size_t)(m0 + row) * K + kk + q * 8);
        }
#pragma unroll
        for (int i = 0; i < 4; i++) {
            int l = tid + i * GTPB;
            int row = l >> 3, q = l & 7;
            uint32_t soff = (uint32_t)row * 128u + (uint32_t)((q ^ (row & 7)) << 4);
            cp16(sB + soff, Bt + (size_t)(n0 + row) * K + kk + q * 8);
        }
        cp_commit();
    };

    stage_tile(0, 0);
    stage_tile(1, GBK);

    int rd_stage = 0, wr_stage = 2;
    for (int kt = 0; kt < nK; kt++) {
        if (kt + 1 < nK) cp_wait<1>(); else cp_wait<0>();
        __syncthreads();

        if (kt + 2 < nK) stage_tile(wr_stage, (kt + 2) * GBK);
        if (++wr_stage == NSTAGE) wr_stage = 0;

        uint32_t As_b = smem_base + (uint32_t)rd_stage * STAGE_BYTES;
        uint32_t Bs_b = As_b + A_HALVES * 2;
        if (++rd_stage == NSTAGE) rd_stage = 0;

#pragma unroll
        for (int kc = 0; kc < 4; kc++) {
            uint32_t ca = (uint32_t)(((2 * kc + ha) ^ keyx) << 4);
            uint32_t cb = (uint32_t)(((2 * kc + hb) ^ keyx) << 4);
            uint32_t a[4][4];
#pragma unroll
            for (int mt = 0; mt < 4; mt++)
                ldsm4(a[mt][0], a[mt][1], a[mt][2], a[mt][3], As_b + aab[mt] + ca);
#pragma unroll
            for (int p = 0; p < 2; p++) {
                uint32_t bv0, bv1, bv2, bv3;
                ldsm4(bv0, bv1, bv2, bv3, Bs_b + bab[p] + cb);
#pragma unroll
                for (int mt = 0; mt < 4; mt++) {
                    mma16(acc[mt][2 * p],     a[mt][0], a[mt][1], a[mt][2], a[mt][3], bv0, bv1);
                    mma16(acc[mt][2 * p + 1], a[mt][0], a[mt][1], a[mt][2], a[mt][3], bv2, bv3);
                }
            }
        }
    }

    // Epilogue
#pragma unroll
    for (int mt = 0; mt < 4; mt++) {
#pragma unroll
        for (int h = 0; h < 2; h++) {
            int m = m0 + wm0 + mt * 16 + (lane >> 2) + h * 8;
#pragma unroll
            for (int nt = 0; nt < 4; nt++) {
                int n = n0 + wn0 + nt * 8 + 2 * (lane & 3);
                float rx = acc[mt][nt][h * 2 + 0] + bias[n];
                float ry = acc[mt][nt][h * 2 + 1] + bias[n + 1];
                if (mode == 1) {
                    int which = n >> 10;
                    int hh = (n >> 6) & (HH - 1);
                    int d = n & (DD - 1);
                    int b = m >> 11;
                    int t = m & (TT - 1);
                    __half* p = g_qkvh + (size_t)which * BHTD
                              + ((((size_t)b * HH + hh) * TT + t) * DD + d);
                    *(__half2*)p = __floats2half2_rn(rx, ry);
                } else {
                    float2 r; r.x = rx; r.y = ry;
                    *(float2*)(Cout + (size_t)m * N + n) = r;
                }
            }
        }
    }
}

// ===========================================================================
// FP16 flash attention (unchanged from R16): q-block 128, 4 warps x 32 rows,
// 2 CTAs/SM.
// ===========================================================================
#define ATPB 128
#define ROWB 128
#define KVTILE (64 * ROWB)
#define KVSTG  (2 * KVTILE)
#define PSMB   (4 * 32 * ROWB)
#define SMEM_ATTN (2 * KVSTG + PSMB)
#define QSCALE (0.125f * 1.44269504088896f)

__global__ __launch_bounds__(ATPB, 2) void attn_h()
{
    extern __shared__ char smc[];
    uint32_t smem_base = (uint32_t)__cvta_generic_to_shared(smc);
    uint32_t psm_base = smem_base + 2 * KVSTG;

    int qb = gridDim.x - 1 - blockIdx.x;
    int bh = blockIdx.y;
    int q0 = qb * 128;
    int tid = threadIdx.x, lane = tid & 31, w = tid >> 5;
    int qw0 = q0 + w * 32;

    const __half* qp = g_qkvh + (size_t)bh * TT * DD;
    const __half* kp = qp + (size_t)BHTD;
    const __half* vp = qp + 2ull * BHTD;

    auto stage_kv = [&](int st, int k0) {
        uint32_t kb = smem_base + (uint32_t)st * KVSTG;
        uint32_t vb = kb + KVTILE;
#pragma unroll
        for (int it = 0; it < 4; it++) {
            int l = tid + it * ATPB;
            int row = l >> 3, q = l & 7;
            uint32_t soff = (uint32_t)row * 128u + (uint32_t)((q ^ (row & 7)) << 4);
            cp16ca(kb + soff, kp + (size_t)(k0 + row) * DD + q * 8);
            cp16ca(vb + soff, vp + (size_t)(k0 + row) * DD + q * 8);
        }
        cp_commit();
    };

    stage_kv(0, 0);

    int keyx = lane & 7;
    uint32_t krow[4];
#pragma unroll
    for (int p = 0; p < 4; p++)
        krow[p] = (uint32_t)(p * 16 + (lane & 7) + ((lane >> 4) << 3)) * 128u;
    uint32_t vrow = (uint32_t)((lane & 7) + (((lane >> 3) & 1) << 3)) * 128u;
    uint32_t hb = (lane >> 3) & 1;
    uint32_t ha = lane >> 4;

    uint32_t qa[2][4][4];
#pragma unroll
    for (int g = 0; g < 2; g++) {
        int r = qw0 + g * 16 + (lane >> 2);
#pragma unroll
        for (int kc = 0; kc < 4; kc++) {
            int kb = kc * 16 + 2 * (lane & 3);
#pragma unroll
            for (int s = 0; s < 4; s++) {
                int rr = r + ((s & 1) ? 8 : 0);
                int cc = kb + ((s & 2) ? 8 : 0);
                float f0 = __half2float(qp[(size_t)rr * DD + cc])     * QSCALE;
                float f1 = __half2float(qp[(size_t)rr * DD + cc + 1]) * QSCALE;
                __half2 hq = __floats2half2_rn(f0, f1);
                qa[g][kc][s] = *(uint32_t*)&hq;
            }
        }
    }

    float m_i[2][2], l_i[2][2];
    float oacc[2][8][4];
#pragma unroll
    for (int g = 0; g < 2; g++) {
        m_i[g][0] = m_i[g][1] = -1e30f;
        l_i[g][0] = l_i[g][1] = 0.f;
#pragma unroll
        for (int nt = 0; nt < 8; nt++)
#pragma unroll
            for (int j = 0; j < 4; j++) oacc[g][nt][j] = 0.f;
    }

    int jbmax = 2 * qb + 1;
    for (int jb = 0; jb <= jbmax; jb++) {
        int k0 = jb * 64;
        cp_wait<0>();
        __syncthreads();

        if (jb < jbmax) stage_kv((jb + 1) & 1, k0 + 64);

        uint32_t Kb = smem_base + (uint32_t)((jb & 1) * KVSTG);
        uint32_t Vb = Kb + KVTILE;

        if (k0 <= qw0 + 31) {
            float sacc[2][8][4];
#pragma unroll
            for (int g = 0; g < 2; g++)
#pragma unroll
                for (int nt = 0; nt < 8; nt++)
#pragma unroll
                    for (int j = 0; j < 4; j++) sacc[g][nt][j] = 0.f;
#pragma unroll
            for (int kc = 0; kc < 4; kc++) {
                uint32_t cb = (uint32_t)(((2 * kc + hb) ^ keyx) << 4);
#pragma unroll
                for (int p = 0; p < 4; p++) {
                    uint32_t b0, b1, b2, b3;
                    ldsm4(b0, b1, b2, b3, Kb + krow[p] + cb);
                    mma16(sacc[0][2 * p],     qa[0][kc][0], qa[0][kc][1], qa[0][kc][2], qa[0][kc][3], b0, b1);
                    mma16(sacc[1][2 * p],     qa[1][kc][0], qa[1][kc][1], qa[1][kc][2], qa[1][kc][3], b0, b1);
                    mma16(sacc[0][2 * p + 1], qa[0][kc][0], qa[0][kc][1], qa[0][kc][2], qa[0][kc][3], b2, b3);
                    mma16(sacc[1][2 * p + 1], qa[1][kc][0], qa[1][kc][1], qa[1][kc][2], qa[1][kc][3], b2, b3);
                }
            }

            if (k0 + 63 > qw0) {
#pragma unroll
                for (int g = 0; g < 2; g++) {
                    int r0 = qw0 + g * 16 + (lane >> 2);
#pragma unroll
                    for (int nt = 0; nt < 8; nt++) {
                        int col = k0 + nt * 8 + 2 * (lane & 3);
                        if (col     > r0)     sacc[g][nt][0] = -1e30f;
                        if (col + 1 > r0)     sacc[g][nt][1] = -1e30f;
                        if (col     > r0 + 8) sacc[g][nt][2] = -1e30f;
                        if (col + 1 > r0 + 8) sacc[g][nt][3] = -1e30f;
                    }
                }
            }

#pragma unroll
            for (int g = 0; g < 2; g++) {
#pragma unroll
                for (int h = 0; h < 2; h++) {
                    float mx = -1e30f;
#pragma unroll
                    for (int nt = 0; nt < 8; nt++) {
                        mx = fmaxf(mx, sacc[g][nt][h * 2 + 0]);
                        mx = fmaxf(mx, sacc[g][nt][h * 2 + 1]);
                    }
                    mx = fmaxf(mx, __shfl_xor_sync(0xffffffffu, mx, 1));
                    mx = fmaxf(mx, __shfl_xor_sync(0xffffffffu, mx, 2));
                    float mnew = fmaxf(m_i[g][h], mx);
                    float alpha = ex2(m_i[g][h] - mnew);
                    float rs = 0.f;
#pragma unroll
                    for (int nt = 0; nt < 8; nt++) {
                        float p0 = ex2(sacc[g][nt][h * 2 + 0] - mnew);
                        float p1 = ex2(sacc[g][nt][h * 2 + 1] - mnew);
                        sacc[g][nt][h * 2 + 0] = p0;
                        sacc[g][nt][h * 2 + 1] = p1;
                        rs += p0 + p1;
                    }
                    rs += __shfl_xor_sync(0xffffffffu, rs, 1);
                    rs += __shfl_xor_sync(0xffffffffu, rs, 2);
                    l_i[g][h] = l_i[g][h] * alpha + rs;
                    m_i[g][h] = mnew;
#pragma unroll
                    for (int nt = 0; nt < 8; nt++) {
                        oacc[g][nt][h * 2 + 0] *= alpha;
                        oacc[g][nt][h * 2 + 1] *= alpha;
                    }
                }
            }

            uint32_t Pw = psm_base + (uint32_t)w * 32 * ROWB;
#pragma unroll
            for (int g = 0; g < 2; g++) {
                int r0 = g * 16 + (lane >> 2);
#pragma unroll
                for (int nt = 0; nt < 8; nt++) {
                    uint32_t coff = (uint32_t)(((nt ^ (r0 & 7)) << 4) + 4 * (lane & 3));
                    __half2 p0 = __floats2half2_rn(sacc[g][nt][0], sacc[g][nt][1]);
                    __half2 p1 = __floats2half2_rn(sacc[g][nt][2], sacc[g][nt][3]);
                    *(__half2*)(smc + (Pw - smem_base) + (uint32_t)r0 * 128u + coff) = p0;
                    *(__half2*)(smc + (Pw - smem_base) + (uint32_t)(r0 + 8) * 128u + coff) = p1;
                }
            }
            __syncwarp();

#pragma unroll
            for (int kc = 0; kc < 4; kc++) {
                uint32_t ca = (uint32_t)(((2 * kc + ha) ^ keyx) << 4);
                uint32_t a[2][4];
#pragma unroll
                for (int g = 0; g < 2; g++)
                    ldsm4(a[g][0], a[g][1], a[g][2], a[g][3],
                          Pw + (uint32_t)(g * 16 + (lane & 15)) * 128u + ca);
                uint32_t vb_kc = Vb + vrow + (uint32_t)(kc * 16) * 128u;
#pragma unroll
                for (int pd = 0; pd < 4; pd++) {
                    uint32_t cv = (uint32_t)(((2 * pd + ha) ^ keyx) << 4);
                    uint32_t bv0, bv1, bv2, bv3;
                    ldsm4t(bv0, bv1, bv2, bv3, vb_kc + cv);
                    mma16(oacc[0][2 * pd],     a[0][0], a[0][1], a[0][2], a[0][3], bv0, bv1);
                    mma16(oacc[1][2 * pd],     a[1][0], a[1][1], a[1][2], a[1][3], bv0, bv1);
                    mma16(oacc[0][2 * pd + 1], a[0][0], a[0][1], a[0][2], a[0][3], bv2, bv3);
                    mma16(oacc[1][2 * pd + 1], a[1][0], a[1][1], a[1][2], a[1][3], bv2, bv3);
                }
            }
            __syncwarp();
        }
    }

    int bb = bh >> 4, hh = bh & (HH - 1);
#pragma unroll
    for (int g = 0; g < 2; g++) {
#pragma unroll
        for (int h = 0; h < 2; h++) {
            int row = qw0 + g * 16 + (lane >> 2) + h * 8;
            float inv = 1.f / l_i[g][h];
#pragma unroll
            for (int nt = 0; nt < 8; nt++) {
                int col = hh * DD + nt * 8 + 2 * (lane & 3);
                __half2 r = __floats2half2_rn(oacc[g][nt][h * 2 + 0] * inv,
                                              oacc[g][nt][h * 2 + 1] * inv);
                *(__half2*)(g_atth + ((size_t)bb * TT + row) * CC + col) = r;
            }
        }
    }
}

// ===========================================================================
// Launch
// ===========================================================================
extern "C" void kernel_launch(void* const* d_in, const int* in_sizes, int n_in,
                              void* d_out, int out_size)
{
    (void)in_sizes; (void)n_in; (void)out_size;
    const float* x      = (const float*)d_in[0];
    const float* qkv_w  = (const float*)d_in[1];
    const float* qkv_b  = (const float*)d_in[2];
    const float* proj_w = (const float*)d_in[3];
    const float* proj_b = (const float*)d_in[4];
    float* out = (float*)d_out;

    cudaFuncSetAttribute(gemm_h,
                         cudaFuncAttributeMaxDynamicSharedMemorySize, SMEM_GEMM);
    cudaFuncSetAttribute(attn_h,
                         cudaFuncAttributeMaxDynamicSharedMemorySize, SMEM_ATTN);

    // Device addresses of __device__ symbols (query, not allocation).
    __half *xh, *wqh, *wph, *atth;
    cudaGetSymbolAddress((void**)&xh,   g_xh);
    cudaGetSymbolAddress((void**)&wqh,  g_wqh);
    cudaGetSymbolAddress((void**)&wph,  g_wph);
    cudaGetSymbolAddress((void**)&atth, g_atth);

    // 0) convert operands to fp16 (single launch)
    cvt_all<<<2048, 256>>>((const float4*)x, (const float4*)qkv_w,
                           (const float4*)proj_w);

    // 1) QKV projection + bias -> scatter fp16 [3][B,H,T,D]
    gemm_h<<<dim3(3 * CC / GBN, BB * TT / GBM), GTPB, SMEM_GEMM>>>(
        xh, wqh, qkv_b, nullptr, BB * TT, 3 * CC, CC, 1);

    // 2) Causal flash attention -> g_atth [B,T,C]
    attn_h<<<dim3(TT / 128, BB * HH), ATPB, SMEM_ATTN>>>();

    // 3) Output projection + bias -> d_out (fp32)
    gemm_h<<<dim3(CC / GBN, BB * TT / GBM), GTPB, SMEM_GEMM>>>(
        atth, wph, proj_b, out, BB * TT, CC, CC, 2);
}